// round 9
// baseline (speedup 1.0000x reference)
#include <cuda_runtime.h>
#include <cuda_bf16.h>
#include <stdint.h>

#define NN 50000
#define EE 800000
#define DIMK 64
#define BN_EPS 1e-5f
#define L2_EPS 1e-12f

// ---- scratch (device globals; no allocation allowed) ----
__device__ __align__(16) float g_h[NN * DIMK];     // h = x @ W
__device__ __align__(16) float g_acc[NN * DIMK];   // aggregated rows
__device__ int   g_degi[NN];                       // edge count per dst (excl. self)
__device__ int   g_cur[NN];                        // fill cursors (= rowptr after scan)
__device__ int   g_rowptr[NN + 1];
__device__ int   g_csri[EE];                       // src indices grouped by dst
__device__ float g_dinv[NN];
__device__ float g_sum[DIMK];
__device__ float g_sumsq[DIMK];
__device__ int   g_is32;                           // 1 if edge_index is int32

// ---- 0) fused: dtype probe + zero degree counters + zero BN stats ----
__global__ void k_init(const unsigned int* __restrict__ ei32, int n) {
    int i = blockIdx.x * blockDim.x + threadIdx.x;
    if (i < n) g_degi[i] = 0;
    if (i < DIMK) { g_sum[i] = 0.0f; g_sumsq[i] = 0.0f; }
    if (blockIdx.x == 0) {
        int tid = threadIdx.x;
        unsigned int acc = 0;
        for (int j = tid; j < 2048; j += 256) acc |= ei32[2 * j + 1];
        __shared__ unsigned int sh[256];
        sh[tid] = acc;
        __syncthreads();
        for (int s = 128; s > 0; s >>= 1) {
            if (tid < s) sh[tid] |= sh[tid + s];
            __syncthreads();
        }
        if (tid == 0) g_is32 = (sh[0] != 0) ? 1 : 0;
    }
}

__device__ __forceinline__ int load_idx(const void* ei, long long pos, int is32) {
    if (is32) return ((const int*)ei)[pos];
    return (int)((const long long*)ei)[pos];
}

// ---- 1) degree: int atomicAdd 1 per edge at dst ----
__global__ void k_deg(const void* __restrict__ ei, int E) {
    int e = blockIdx.x * blockDim.x + threadIdx.x;
    if (e >= E) return;
    int dst = load_idx(ei, (long long)E + e, g_is32);
    atomicAdd(&g_degi[dst], 1);
}

// ---- 2) scan degrees -> rowptr (+cursors) + dinv. One block, SMEM-staged. ----
__global__ void k_scan(int n, int E) {
    extern __shared__ int sc[];          // n ints (~200 KB)
    __shared__ int part[1024];
    int t = threadIdx.x;
    for (int i = t; i < n; i += 1024) sc[i] = g_degi[i];
    __syncthreads();
    const int chunk = (n + 1023) / 1024;
    int start = t * chunk; if (start > n) start = n;
    int end = start + chunk; if (end > n) end = n;
    int s = 0;
    for (int i = start; i < end; i++) s += sc[i];
    part[t] = s;
    __syncthreads();
    for (int off = 1; off < 1024; off <<= 1) {
        int v = (t >= off) ? part[t - off] : 0;
        __syncthreads();
        part[t] += v;
        __syncthreads();
    }
    int run = part[t] - s;               // exclusive prefix of this chunk
    for (int i = start; i < end; i++) {
        int c = sc[i];
        g_dinv[i] = rsqrtf((float)(c + 1));
        sc[i] = run;
        run += c;
    }
    __syncthreads();
    for (int i = t; i < n; i += 1024) {
        int rp = sc[i];
        g_rowptr[i] = rp;
        g_cur[i]    = rp;
    }
    if (t == 0) g_rowptr[n] = E;
}

// ---- 3) GEMM h = x@W (register-tiled 4x4) — runs on side stream ----
__global__ void k_gemm(const float* __restrict__ x, const float* __restrict__ W, int n) {
    __shared__ float Wsh[DIMK][68];
    __shared__ float xsh[DIMK][68];
    int tid = threadIdx.x;
    int row0 = blockIdx.x * 64;

    for (int i = tid; i < 1024; i += 256) {
        int r  = i >> 4;
        int c4 = (i & 15) << 2;
        *(float4*)&Wsh[r][c4] = ((const float4*)W)[i];
    }
    for (int i = tid; i < 1024; i += 256) {
        int r  = i >> 4;
        int c4 = (i & 15) << 2;
        int gr = row0 + r;
        float4 v = (gr < n) ? ((const float4*)x)[(size_t)gr * 16 + (i & 15)]
                            : make_float4(0.f, 0.f, 0.f, 0.f);
        *(float4*)&xsh[r][c4] = v;
    }
    __syncthreads();

    int tr = tid >> 4;
    int tc = (tid & 15) << 2;
    float acc[4][4] = {};
    #pragma unroll
    for (int k = 0; k < DIMK; k++) {
        float4 wv = *(const float4*)&Wsh[k][tc];
        float xv[4];
        #pragma unroll
        for (int i = 0; i < 4; i++) xv[i] = xsh[i * 16 + tr][k];
        #pragma unroll
        for (int i = 0; i < 4; i++) {
            acc[i][0] = fmaf(xv[i], wv.x, acc[i][0]);
            acc[i][1] = fmaf(xv[i], wv.y, acc[i][1]);
            acc[i][2] = fmaf(xv[i], wv.z, acc[i][2]);
            acc[i][3] = fmaf(xv[i], wv.w, acc[i][3]);
        }
    }
    #pragma unroll
    for (int i = 0; i < 4; i++) {
        int r = row0 + i * 16 + tr;
        if (r >= n) continue;
        *(float4*)&g_h[(size_t)r * DIMK + tc] =
            make_float4(acc[i][0], acc[i][1], acc[i][2], acc[i][3]);
    }
}

// ---- 4) fill CSR: src grouped by dst (single cursor atomic per edge) ----
__global__ void k_fill(const void* __restrict__ ei, int E) {
    int e = blockIdx.x * blockDim.x + threadIdx.x;
    if (e >= E) return;
    int is32 = g_is32;
    int src = load_idx(ei, e, is32);
    int dst = load_idx(ei, (long long)E + e, is32);
    int pos = atomicAdd(&g_cur[dst], 1);
    g_csri[pos] = src;
}

// ---- 5) aggregate: warp per dst; self-loop + edges (register acc) + BN stats ----
__global__ void k_agg(int n) {
    __shared__ float shs[8][DIMK];
    __shared__ float shq[8][DIMK];
    int lane = threadIdx.x & 31;
    int w    = threadIdx.x >> 5;             // 0..7
    int dst  = blockIdx.x * 8 + w;

    float a0 = 0.f, a1 = 0.f;
    if (dst < n) {
        float dv = g_dinv[dst];
        size_t hb = (size_t)dst * DIMK;
        a0 = g_h[hb + lane] * (dv * dv);
        a1 = g_h[hb + lane + 32] * (dv * dv);
        int p  = g_rowptr[dst];
        int p1 = g_rowptr[dst + 1];
        for (; p + 3 < p1; p += 4) {
            int s0i = g_csri[p];
            int s1i = g_csri[p + 1];
            int s2i = g_csri[p + 2];
            int s3i = g_csri[p + 3];
            float n0 = g_dinv[s0i] * dv;
            float n1 = g_dinv[s1i] * dv;
            float n2 = g_dinv[s2i] * dv;
            float n3 = g_dinv[s3i] * dv;
            size_t b0 = (size_t)s0i * DIMK;
            size_t b1 = (size_t)s1i * DIMK;
            size_t b2 = (size_t)s2i * DIMK;
            size_t b3 = (size_t)s3i * DIMK;
            float h00 = g_h[b0 + lane], h01 = g_h[b0 + lane + 32];
            float h10 = g_h[b1 + lane], h11 = g_h[b1 + lane + 32];
            float h20 = g_h[b2 + lane], h21 = g_h[b2 + lane + 32];
            float h30 = g_h[b3 + lane], h31 = g_h[b3 + lane + 32];
            a0 = fmaf(n0, h00, a0); a1 = fmaf(n0, h01, a1);
            a0 = fmaf(n1, h10, a0); a1 = fmaf(n1, h11, a1);
            a0 = fmaf(n2, h20, a0); a1 = fmaf(n2, h21, a1);
            a0 = fmaf(n3, h30, a0); a1 = fmaf(n3, h31, a1);
        }
        for (; p < p1; p++) {
            int s0i = g_csri[p];
            float n0 = g_dinv[s0i] * dv;
            size_t b0 = (size_t)s0i * DIMK;
            a0 = fmaf(n0, g_h[b0 + lane], a0);
            a1 = fmaf(n0, g_h[b0 + lane + 32], a1);
        }
        g_acc[hb + lane]      = a0;
        g_acc[hb + lane + 32] = a1;
    }

    shs[w][lane] = a0; shs[w][lane + 32] = a1;
    shq[w][lane] = a0 * a0; shq[w][lane + 32] = a1 * a1;
    __syncthreads();
    if (threadIdx.x < DIMK) {
        float ts = 0.f, tq = 0.f;
        #pragma unroll
        for (int i = 0; i < 8; i++) { ts += shs[i][threadIdx.x]; tq += shq[i][threadIdx.x]; }
        atomicAdd(&g_sum[threadIdx.x], ts);
        atomicAdd(&g_sumsq[threadIdx.x], tq);
    }
}

// ---- 6) finalize: BN (b cancels) -> ReLU -> L2 row-normalize -> out ----
__global__ void k_final(const float* __restrict__ gamma, const float* __restrict__ beta,
                        float* __restrict__ out, int n) {
    int warp = (blockIdx.x * blockDim.x + threadIdx.x) >> 5;
    int lane = threadIdx.x & 31;
    if (warp >= n) return;
    const float invN = 1.0f / (float)n;

    int c0 = lane, c1 = lane + 32;
    float m0 = g_sum[c0] * invN, m1 = g_sum[c1] * invN;
    float v0 = g_sumsq[c0] * invN - m0 * m0;
    float v1 = g_sumsq[c1] * invN - m1 * m1;
    float sc0 = rsqrtf(v0 + BN_EPS) * gamma[c0];
    float sc1 = rsqrtf(v1 + BN_EPS) * gamma[c1];

    size_t base = (size_t)warp * DIMK;
    float a0 = g_acc[base + c0];
    float a1 = g_acc[base + c1];
    float y0 = fmaf(a0 - m0, sc0, beta[c0]);
    float y1 = fmaf(a1 - m1, sc1, beta[c1]);
    y0 = fmaxf(y0, 0.0f);
    y1 = fmaxf(y1, 0.0f);

    float ss = y0 * y0 + y1 * y1;
    #pragma unroll
    for (int o = 16; o > 0; o >>= 1)
        ss += __shfl_xor_sync(0xffffffffu, ss, o);
    float nrm = sqrtf(ss);
    float inv = 1.0f / fmaxf(nrm, L2_EPS);
    out[base + c0] = y0 * inv;
    out[base + c1] = y1 * inv;
}

extern "C" void kernel_launch(void* const* d_in, const int* in_sizes, int n_in,
                              void* d_out, int out_size) {
    const float* x     = (const float*)d_in[0];
    const void*  ei    = d_in[1];                 // int32 or int64, probed at runtime
    const float* W     = (const float*)d_in[2];
    // const float* b  = (const float*)d_in[3];   // cancels exactly in BN
    const float* gamma = (const float*)d_in[4];
    const float* beta  = (const float*)d_in[5];
    float* out = (float*)d_out;

    int n = in_sizes[0] / DIMK;       // 50000
    int E = in_sizes[1] / 2;          // 800000

    static int s_inited = 0;
    static cudaStream_t s_side;
    static cudaEvent_t  s_fork, s_join;
    int scan_smem = ((n + 1023) & ~1023) * 4 + 64;
    if (!s_inited) {
        cudaFuncSetAttribute(k_scan, cudaFuncAttributeMaxDynamicSharedMemorySize, scan_smem);
        cudaStreamCreateWithFlags(&s_side, cudaStreamNonBlocking);
        cudaEventCreateWithFlags(&s_fork, cudaEventDisableTiming);
        cudaEventCreateWithFlags(&s_join, cudaEventDisableTiming);
        s_inited = 1;
    }

    // Fork: gemm (x,W -> g_h) is independent of the CSR build chain.
    cudaEventRecord(s_fork, 0);
    cudaStreamWaitEvent(s_side, s_fork, 0);
    k_gemm<<<(n + 63) / 64, 256, 0, s_side>>>(x, W, n);
    cudaEventRecord(s_join, s_side);

    // Main stream: CSR build.
    k_init <<<(n + 255) / 256, 256>>>((const unsigned int*)ei, n);
    k_deg  <<<(E + 255) / 256, 256>>>(ei, E);
    k_scan <<<1, 1024, scan_smem>>>(n, E);
    k_fill <<<(E + 255) / 256, 256>>>(ei, E);

    // Join, then aggregate + finalize.
    cudaStreamWaitEvent(0, s_join, 0);
    k_agg  <<<(n + 7) / 8, 256>>>(n);
    k_final<<<(n + 7) / 8, 256>>>(gamma, beta, out, n);
}

// round 10
// speedup vs baseline: 1.2671x; 1.2671x over previous
#include <cuda_runtime.h>
#include <cuda_bf16.h>
#include <stdint.h>

#define NN 50000
#define EE 800000
#define DIMK 64
#define BN_EPS 1e-5f
#define L2_EPS 1e-12f

// ---- scratch (device globals; no allocation allowed) ----
__device__ __align__(16) float g_h[NN * DIMK];     // h = x @ W
__device__ __align__(16) float g_acc[NN * DIMK];   // aggregated rows
__device__ int   g_degi[NN];                       // edge count per dst (excl. self)
__device__ int   g_cur[NN];                        // fill cursors (= rowptr after scan)
__device__ int   g_rowptr[NN + 1];
__device__ int   g_csri[EE];                       // src indices grouped by dst
__device__ float g_dinv[NN];
__device__ float g_sum[DIMK];
__device__ float g_sumsq[DIMK];
__device__ int   g_is32;                           // 1 if edge_index is int32

// ---- 0) fused: dtype probe + zero degree counters + zero BN stats ----
__global__ void k_init(const unsigned int* __restrict__ ei32, int n) {
    int i = blockIdx.x * blockDim.x + threadIdx.x;
    if (i < n) g_degi[i] = 0;
    if (i < DIMK) { g_sum[i] = 0.0f; g_sumsq[i] = 0.0f; }
    if (blockIdx.x == 0) {
        int tid = threadIdx.x;
        unsigned int acc = 0;
        for (int j = tid; j < 2048; j += 256) acc |= ei32[2 * j + 1];
        __shared__ unsigned int sh[256];
        sh[tid] = acc;
        __syncthreads();
        for (int s = 128; s > 0; s >>= 1) {
            if (tid < s) sh[tid] |= sh[tid + s];
            __syncthreads();
        }
        if (tid == 0) g_is32 = (sh[0] != 0) ? 1 : 0;
    }
}

__device__ __forceinline__ int load_idx(const void* ei, long long pos, int is32) {
    if (is32) return ((const int*)ei)[pos];
    return (int)((const long long*)ei)[pos];
}

// ---- 1) degree: int atomicAdd 1 per edge at dst ----
__global__ void k_deg(const void* __restrict__ ei, int E) {
    int e = blockIdx.x * blockDim.x + threadIdx.x;
    if (e >= E) return;
    int dst = load_idx(ei, (long long)E + e, g_is32);
    atomicAdd(&g_degi[dst], 1);
}

// ---- 2) integer-only scan: degrees -> rowptr + cursors. One block, SMEM-staged. ----
// NO transcendentals here: 50k MUFU on one SM costs ~50us (measured R9).
__global__ void k_scan(int n, int E) {
    extern __shared__ int sc[];          // n ints (~200 KB)
    __shared__ int part[1024];
    int t = threadIdx.x;
    for (int i = t; i < n; i += 1024) sc[i] = g_degi[i];
    __syncthreads();
    const int chunk = (n + 1023) / 1024;
    int start = t * chunk; if (start > n) start = n;
    int end = start + chunk; if (end > n) end = n;
    int s = 0;
    for (int i = start; i < end; i++) s += sc[i];
    part[t] = s;
    __syncthreads();
    for (int off = 1; off < 1024; off <<= 1) {
        int v = (t >= off) ? part[t - off] : 0;
        __syncthreads();
        part[t] += v;
        __syncthreads();
    }
    int run = part[t] - s;               // exclusive prefix of this chunk
    for (int i = start; i < end; i++) {
        int c = sc[i];
        sc[i] = run;
        run += c;
    }
    __syncthreads();
    for (int i = t; i < n; i += 1024) {
        int rp = sc[i];
        g_rowptr[i] = rp;
        g_cur[i]    = rp;
    }
    if (t == 0) g_rowptr[n] = E;
}

// ---- 3) GEMM h = x@W (register-tiled 4x4) — runs on side stream ----
__global__ void k_gemm(const float* __restrict__ x, const float* __restrict__ W, int n) {
    __shared__ float Wsh[DIMK][68];
    __shared__ float xsh[DIMK][68];
    int tid = threadIdx.x;
    int row0 = blockIdx.x * 64;

    for (int i = tid; i < 1024; i += 256) {
        int r  = i >> 4;
        int c4 = (i & 15) << 2;
        *(float4*)&Wsh[r][c4] = ((const float4*)W)[i];
    }
    for (int i = tid; i < 1024; i += 256) {
        int r  = i >> 4;
        int c4 = (i & 15) << 2;
        int gr = row0 + r;
        float4 v = (gr < n) ? ((const float4*)x)[(size_t)gr * 16 + (i & 15)]
                            : make_float4(0.f, 0.f, 0.f, 0.f);
        *(float4*)&xsh[r][c4] = v;
    }
    __syncthreads();

    int tr = tid >> 4;
    int tc = (tid & 15) << 2;
    float acc[4][4] = {};
    #pragma unroll
    for (int k = 0; k < DIMK; k++) {
        float4 wv = *(const float4*)&Wsh[k][tc];
        float xv[4];
        #pragma unroll
        for (int i = 0; i < 4; i++) xv[i] = xsh[i * 16 + tr][k];
        #pragma unroll
        for (int i = 0; i < 4; i++) {
            acc[i][0] = fmaf(xv[i], wv.x, acc[i][0]);
            acc[i][1] = fmaf(xv[i], wv.y, acc[i][1]);
            acc[i][2] = fmaf(xv[i], wv.z, acc[i][2]);
            acc[i][3] = fmaf(xv[i], wv.w, acc[i][3]);
        }
    }
    #pragma unroll
    for (int i = 0; i < 4; i++) {
        int r = row0 + i * 16 + tr;
        if (r >= n) continue;
        *(float4*)&g_h[(size_t)r * DIMK + tc] =
            make_float4(acc[i][0], acc[i][1], acc[i][2], acc[i][3]);
    }
}

// ---- 4) fill CSR (src grouped by dst) + dinv (spread across full grid) ----
__global__ void k_fill(const void* __restrict__ ei, int E, int n) {
    int e = blockIdx.x * blockDim.x + threadIdx.x;
    if (e < n) g_dinv[e] = rsqrtf((float)(1 + g_degi[e]));
    if (e >= E) return;
    int is32 = g_is32;
    int src = load_idx(ei, e, is32);
    int dst = load_idx(ei, (long long)E + e, is32);
    int pos = atomicAdd(&g_cur[dst], 1);
    g_csri[pos] = src;
}

// ---- 5) aggregate: warp per dst; self-loop + edges (register acc) + BN stats ----
__global__ void k_agg(int n) {
    __shared__ float shs[8][DIMK];
    __shared__ float shq[8][DIMK];
    int lane = threadIdx.x & 31;
    int w    = threadIdx.x >> 5;             // 0..7
    int dst  = blockIdx.x * 8 + w;

    float a0 = 0.f, a1 = 0.f;
    if (dst < n) {
        float dv = g_dinv[dst];
        size_t hb = (size_t)dst * DIMK;
        a0 = g_h[hb + lane] * (dv * dv);
        a1 = g_h[hb + lane + 32] * (dv * dv);
        int p  = g_rowptr[dst];
        int p1 = g_rowptr[dst + 1];
        for (; p + 3 < p1; p += 4) {
            int s0i = g_csri[p];
            int s1i = g_csri[p + 1];
            int s2i = g_csri[p + 2];
            int s3i = g_csri[p + 3];
            float n0 = g_dinv[s0i] * dv;
            float n1 = g_dinv[s1i] * dv;
            float n2 = g_dinv[s2i] * dv;
            float n3 = g_dinv[s3i] * dv;
            size_t b0 = (size_t)s0i * DIMK;
            size_t b1 = (size_t)s1i * DIMK;
            size_t b2 = (size_t)s2i * DIMK;
            size_t b3 = (size_t)s3i * DIMK;
            float h00 = g_h[b0 + lane], h01 = g_h[b0 + lane + 32];
            float h10 = g_h[b1 + lane], h11 = g_h[b1 + lane + 32];
            float h20 = g_h[b2 + lane], h21 = g_h[b2 + lane + 32];
            float h30 = g_h[b3 + lane], h31 = g_h[b3 + lane + 32];
            a0 = fmaf(n0, h00, a0); a1 = fmaf(n0, h01, a1);
            a0 = fmaf(n1, h10, a0); a1 = fmaf(n1, h11, a1);
            a0 = fmaf(n2, h20, a0); a1 = fmaf(n2, h21, a1);
            a0 = fmaf(n3, h30, a0); a1 = fmaf(n3, h31, a1);
        }
        for (; p < p1; p++) {
            int s0i = g_csri[p];
            float n0 = g_dinv[s0i] * dv;
            size_t b0 = (size_t)s0i * DIMK;
            a0 = fmaf(n0, g_h[b0 + lane], a0);
            a1 = fmaf(n0, g_h[b0 + lane + 32], a1);
        }
        g_acc[hb + lane]      = a0;
        g_acc[hb + lane + 32] = a1;
    }

    shs[w][lane] = a0; shs[w][lane + 32] = a1;
    shq[w][lane] = a0 * a0; shq[w][lane + 32] = a1 * a1;
    __syncthreads();
    if (threadIdx.x < DIMK) {
        float ts = 0.f, tq = 0.f;
        #pragma unroll
        for (int i = 0; i < 8; i++) { ts += shs[i][threadIdx.x]; tq += shq[i][threadIdx.x]; }
        atomicAdd(&g_sum[threadIdx.x], ts);
        atomicAdd(&g_sumsq[threadIdx.x], tq);
    }
}

// ---- 6) finalize: BN (b cancels) -> ReLU -> L2 row-normalize -> out ----
__global__ void k_final(const float* __restrict__ gamma, const float* __restrict__ beta,
                        float* __restrict__ out, int n) {
    int warp = (blockIdx.x * blockDim.x + threadIdx.x) >> 5;
    int lane = threadIdx.x & 31;
    if (warp >= n) return;
    const float invN = 1.0f / (float)n;

    int c0 = lane, c1 = lane + 32;
    float m0 = g_sum[c0] * invN, m1 = g_sum[c1] * invN;
    float v0 = g_sumsq[c0] * invN - m0 * m0;
    float v1 = g_sumsq[c1] * invN - m1 * m1;
    float sc0 = rsqrtf(v0 + BN_EPS) * gamma[c0];
    float sc1 = rsqrtf(v1 + BN_EPS) * gamma[c1];

    size_t base = (size_t)warp * DIMK;
    float a0 = g_acc[base + c0];
    float a1 = g_acc[base + c1];
    float y0 = fmaf(a0 - m0, sc0, beta[c0]);
    float y1 = fmaf(a1 - m1, sc1, beta[c1]);
    y0 = fmaxf(y0, 0.0f);
    y1 = fmaxf(y1, 0.0f);

    float ss = y0 * y0 + y1 * y1;
    #pragma unroll
    for (int o = 16; o > 0; o >>= 1)
        ss += __shfl_xor_sync(0xffffffffu, ss, o);
    float nrm = sqrtf(ss);
    float inv = 1.0f / fmaxf(nrm, L2_EPS);
    out[base + c0] = y0 * inv;
    out[base + c1] = y1 * inv;
}

extern "C" void kernel_launch(void* const* d_in, const int* in_sizes, int n_in,
                              void* d_out, int out_size) {
    const float* x     = (const float*)d_in[0];
    const void*  ei    = d_in[1];                 // int32 or int64, probed at runtime
    const float* W     = (const float*)d_in[2];
    // const float* b  = (const float*)d_in[3];   // cancels exactly in BN
    const float* gamma = (const float*)d_in[4];
    const float* beta  = (const float*)d_in[5];
    float* out = (float*)d_out;

    int n = in_sizes[0] / DIMK;       // 50000
    int E = in_sizes[1] / 2;          // 800000

    static int s_inited = 0;
    static cudaStream_t s_side;
    static cudaEvent_t  s_fork, s_join;
    int scan_smem = ((n + 1023) & ~1023) * 4 + 64;
    if (!s_inited) {
        cudaFuncSetAttribute(k_scan, cudaFuncAttributeMaxDynamicSharedMemorySize, scan_smem);
        cudaStreamCreateWithFlags(&s_side, cudaStreamNonBlocking);
        cudaEventCreateWithFlags(&s_fork, cudaEventDisableTiming);
        cudaEventCreateWithFlags(&s_join, cudaEventDisableTiming);
        s_inited = 1;
    }

    // Fork: gemm (x,W -> g_h) is independent of the CSR build chain.
    cudaEventRecord(s_fork, 0);
    cudaStreamWaitEvent(s_side, s_fork, 0);
    k_gemm<<<(n + 63) / 64, 256, 0, s_side>>>(x, W, n);
    cudaEventRecord(s_join, s_side);

    // Main stream: CSR build.
    k_init <<<(n + 255) / 256, 256>>>((const unsigned int*)ei, n);
    k_deg  <<<(E + 255) / 256, 256>>>(ei, E);
    k_scan <<<1, 1024, scan_smem>>>(n, E);
    k_fill <<<(E + 255) / 256, 256>>>(ei, E, n);

    // Join, then aggregate + finalize.
    cudaStreamWaitEvent(0, s_join, 0);
    k_agg  <<<(n + 7) / 8, 256>>>(n);
    k_final<<<(n + 7) / 8, 256>>>(gamma, beta, out, n);
}

// round 11
// speedup vs baseline: 1.4201x; 1.1207x over previous
#include <cuda_runtime.h>
#include <cuda_fp16.h>
#include <stdint.h>

#define NN 50000
#define EE 800000
#define DIMK 64
#define BN_EPS 1e-5f
#define L2_EPS 1e-12f
#define SCAN_B 1024

// ---- scratch (device globals; no allocation allowed) ----
__device__ __align__(16) float  g_h[NN * DIMK];    // h = x @ W (fp32)
__device__ __align__(16) __half g_hh[NN * DIMK];   // h in fp16 (gather side)
__device__ __align__(16) float  g_acc[NN * DIMK];  // aggregated rows
__device__ int   g_degi[NN];                       // edge count per dst (excl. self)
__device__ int   g_cur[NN];                        // fill cursors (= rowptr)
__device__ int   g_rowptr[NN + 1];
__device__ int   g_blk[128];                       // scan block totals
__device__ int   g_csri[EE];                       // src indices grouped by dst
__device__ float g_dinv[NN];
__device__ float g_sum[DIMK];
__device__ float g_sumsq[DIMK];
__device__ int   g_is32;                           // 1 if edge_index is int32

// ---- 0) fused: dtype probe + zero degree counters + zero BN stats ----
__global__ void k_init(const unsigned int* __restrict__ ei32, int n) {
    int i = blockIdx.x * blockDim.x + threadIdx.x;
    if (i < n) g_degi[i] = 0;
    if (i < DIMK) { g_sum[i] = 0.0f; g_sumsq[i] = 0.0f; }
    if (blockIdx.x == 0) {
        int tid = threadIdx.x;
        unsigned int acc = 0;
        for (int j = tid; j < 2048; j += 256) acc |= ei32[2 * j + 1];
        __shared__ unsigned int sh[256];
        sh[tid] = acc;
        __syncthreads();
        for (int s = 128; s > 0; s >>= 1) {
            if (tid < s) sh[tid] |= sh[tid + s];
            __syncthreads();
        }
        if (tid == 0) g_is32 = (sh[0] != 0) ? 1 : 0;
    }
}

__device__ __forceinline__ int load_idx(const void* ei, long long pos, int is32) {
    if (is32) return ((const int*)ei)[pos];
    return (int)((const long long*)ei)[pos];
}

// ---- 1) degree: int atomicAdd 1 per edge at dst ----
__global__ void k_deg(const void* __restrict__ ei, int E) {
    int e = blockIdx.x * blockDim.x + threadIdx.x;
    if (e >= E) return;
    int dst = load_idx(ei, (long long)E + e, g_is32);
    atomicAdd(&g_degi[dst], 1);
}

// ---- 2a) scanA: per-block exclusive scan + block totals ----
__global__ void k_scanA(int n) {
    __shared__ int sh[SCAN_B];
    int t = threadIdx.x;
    int i = blockIdx.x * SCAN_B + t;
    int v = (i < n) ? g_degi[i] : 0;
    sh[t] = v;
    __syncthreads();
    for (int off = 1; off < SCAN_B; off <<= 1) {
        int u = (t >= off) ? sh[t - off] : 0;
        __syncthreads();
        sh[t] += u;
        __syncthreads();
    }
    if (i < n) g_rowptr[i] = sh[t] - v;            // local exclusive
    if (t == SCAN_B - 1) g_blk[blockIdx.x] = sh[t];
}

// ---- 2b) scanB: add block-prefix offsets; emit rowptr, cursors, dinv ----
__global__ void k_scanB(int n, int E) {
    __shared__ int offs;
    int t = threadIdx.x;
    int b = blockIdx.x;
    if (t == 0) {
        int s = 0;
        for (int j = 0; j < b; j++) s += g_blk[j];
        offs = s;
    }
    __syncthreads();
    int i = b * SCAN_B + t;
    if (i < n) {
        int rp = g_rowptr[i] + offs;
        g_rowptr[i] = rp;
        g_cur[i]    = rp;
        g_dinv[i]   = rsqrtf((float)(1 + g_degi[i]));
    }
    if (i == 0) g_rowptr[n] = E;
}

// ---- 3) GEMM h = x@W (register-tiled 4x4) -> fp32 g_h + fp16 g_hh (side stream) ----
__global__ void k_gemm(const float* __restrict__ x, const float* __restrict__ W, int n) {
    __shared__ float Wsh[DIMK][68];
    __shared__ float xsh[DIMK][68];
    int tid = threadIdx.x;
    int row0 = blockIdx.x * 64;

    for (int i = tid; i < 1024; i += 256) {
        int r  = i >> 4;
        int c4 = (i & 15) << 2;
        *(float4*)&Wsh[r][c4] = ((const float4*)W)[i];
    }
    for (int i = tid; i < 1024; i += 256) {
        int r  = i >> 4;
        int c4 = (i & 15) << 2;
        int gr = row0 + r;
        float4 v = (gr < n) ? ((const float4*)x)[(size_t)gr * 16 + (i & 15)]
                            : make_float4(0.f, 0.f, 0.f, 0.f);
        *(float4*)&xsh[r][c4] = v;
    }
    __syncthreads();

    int tr = tid >> 4;
    int tc = (tid & 15) << 2;
    float acc[4][4] = {};
    #pragma unroll
    for (int k = 0; k < DIMK; k++) {
        float4 wv = *(const float4*)&Wsh[k][tc];
        float xv[4];
        #pragma unroll
        for (int i = 0; i < 4; i++) xv[i] = xsh[i * 16 + tr][k];
        #pragma unroll
        for (int i = 0; i < 4; i++) {
            acc[i][0] = fmaf(xv[i], wv.x, acc[i][0]);
            acc[i][1] = fmaf(xv[i], wv.y, acc[i][1]);
            acc[i][2] = fmaf(xv[i], wv.z, acc[i][2]);
            acc[i][3] = fmaf(xv[i], wv.w, acc[i][3]);
        }
    }
    #pragma unroll
    for (int i = 0; i < 4; i++) {
        int r = row0 + i * 16 + tr;
        if (r >= n) continue;
        size_t o = (size_t)r * DIMK + tc;
        *(float4*)&g_h[o] =
            make_float4(acc[i][0], acc[i][1], acc[i][2], acc[i][3]);
        __half2 hlo = __floats2half2_rn(acc[i][0], acc[i][1]);
        __half2 hhi = __floats2half2_rn(acc[i][2], acc[i][3]);
        uint2 hp; hp.x = *(unsigned int*)&hlo; hp.y = *(unsigned int*)&hhi;
        *(uint2*)&g_hh[o] = hp;
    }
}

// ---- 4) fill CSR: src grouped by dst (single cursor atomic per edge) ----
__global__ void k_fill(const void* __restrict__ ei, int E) {
    int e = blockIdx.x * blockDim.x + threadIdx.x;
    if (e >= E) return;
    int is32 = g_is32;
    int src = load_idx(ei, e, is32);
    int dst = load_idx(ei, (long long)E + e, is32);
    int pos = atomicAdd(&g_cur[dst], 1);
    g_csri[pos] = src;
}

// ---- 5) aggregate: warp per dst; fp16 edge gather, fp32 accumulate + BN stats ----
// lane handles columns (2*lane, 2*lane+1): one 4B fp16 load per row per lane.
__global__ void k_agg(int n) {
    __shared__ float shs[8][DIMK];
    __shared__ float shq[8][DIMK];
    int lane = threadIdx.x & 31;
    int w    = threadIdx.x >> 5;             // 0..7
    int dst  = blockIdx.x * 8 + w;
    int c2   = lane * 2;

    float a0 = 0.f, a1 = 0.f;
    if (dst < n) {
        float dv = g_dinv[dst];
        size_t hb = (size_t)dst * DIMK;
        float2 sl = *(const float2*)&g_h[hb + c2];
        a0 = sl.x * (dv * dv);
        a1 = sl.y * (dv * dv);
        int p  = g_rowptr[dst];
        int p1 = g_rowptr[dst + 1];
        for (; p + 3 < p1; p += 4) {
            int s0i = g_csri[p];
            int s1i = g_csri[p + 1];
            int s2i = g_csri[p + 2];
            int s3i = g_csri[p + 3];
            float n0 = g_dinv[s0i] * dv;
            float n1 = g_dinv[s1i] * dv;
            float n2 = g_dinv[s2i] * dv;
            float n3 = g_dinv[s3i] * dv;
            unsigned int v0 = *(const unsigned int*)&g_hh[(size_t)s0i * DIMK + c2];
            unsigned int v1 = *(const unsigned int*)&g_hh[(size_t)s1i * DIMK + c2];
            unsigned int v2 = *(const unsigned int*)&g_hh[(size_t)s2i * DIMK + c2];
            unsigned int v3 = *(const unsigned int*)&g_hh[(size_t)s3i * DIMK + c2];
            float2 f0 = __half22float2(*(const __half2*)&v0);
            float2 f1 = __half22float2(*(const __half2*)&v1);
            float2 f2 = __half22float2(*(const __half2*)&v2);
            float2 f3 = __half22float2(*(const __half2*)&v3);
            a0 = fmaf(n0, f0.x, a0); a1 = fmaf(n0, f0.y, a1);
            a0 = fmaf(n1, f1.x, a0); a1 = fmaf(n1, f1.y, a1);
            a0 = fmaf(n2, f2.x, a0); a1 = fmaf(n2, f2.y, a1);
            a0 = fmaf(n3, f3.x, a0); a1 = fmaf(n3, f3.y, a1);
        }
        for (; p < p1; p++) {
            int s0i = g_csri[p];
            float n0 = g_dinv[s0i] * dv;
            unsigned int v0 = *(const unsigned int*)&g_hh[(size_t)s0i * DIMK + c2];
            float2 f0 = __half22float2(*(const __half2*)&v0);
            a0 = fmaf(n0, f0.x, a0); a1 = fmaf(n0, f0.y, a1);
        }
        *(float2*)&g_acc[hb + c2] = make_float2(a0, a1);
    }

    shs[w][c2] = a0; shs[w][c2 + 1] = a1;
    shq[w][c2] = a0 * a0; shq[w][c2 + 1] = a1 * a1;
    __syncthreads();
    if (threadIdx.x < DIMK) {
        float ts = 0.f, tq = 0.f;
        #pragma unroll
        for (int i = 0; i < 8; i++) { ts += shs[i][threadIdx.x]; tq += shq[i][threadIdx.x]; }
        atomicAdd(&g_sum[threadIdx.x], ts);
        atomicAdd(&g_sumsq[threadIdx.x], tq);
    }
}

// ---- 6) finalize: BN (b cancels) -> ReLU -> L2 row-normalize -> out ----
__global__ void k_final(const float* __restrict__ gamma, const float* __restrict__ beta,
                        float* __restrict__ out, int n) {
    int warp = (blockIdx.x * blockDim.x + threadIdx.x) >> 5;
    int lane = threadIdx.x & 31;
    if (warp >= n) return;
    const float invN = 1.0f / (float)n;

    int c0 = lane, c1 = lane + 32;
    float m0 = g_sum[c0] * invN, m1 = g_sum[c1] * invN;
    float v0 = g_sumsq[c0] * invN - m0 * m0;
    float v1 = g_sumsq[c1] * invN - m1 * m1;
    float sc0 = rsqrtf(v0 + BN_EPS) * gamma[c0];
    float sc1 = rsqrtf(v1 + BN_EPS) * gamma[c1];

    size_t base = (size_t)warp * DIMK;
    float a0 = g_acc[base + c0];
    float a1 = g_acc[base + c1];
    float y0 = fmaf(a0 - m0, sc0, beta[c0]);
    float y1 = fmaf(a1 - m1, sc1, beta[c1]);
    y0 = fmaxf(y0, 0.0f);
    y1 = fmaxf(y1, 0.0f);

    float ss = y0 * y0 + y1 * y1;
    #pragma unroll
    for (int o = 16; o > 0; o >>= 1)
        ss += __shfl_xor_sync(0xffffffffu, ss, o);
    float nrm = sqrtf(ss);
    float inv = 1.0f / fmaxf(nrm, L2_EPS);
    out[base + c0] = y0 * inv;
    out[base + c1] = y1 * inv;
}

extern "C" void kernel_launch(void* const* d_in, const int* in_sizes, int n_in,
                              void* d_out, int out_size) {
    const float* x     = (const float*)d_in[0];
    const void*  ei    = d_in[1];                 // int32 or int64, probed at runtime
    const float* W     = (const float*)d_in[2];
    // const float* b  = (const float*)d_in[3];   // cancels exactly in BN
    const float* gamma = (const float*)d_in[4];
    const float* beta  = (const float*)d_in[5];
    float* out = (float*)d_out;

    int n = in_sizes[0] / DIMK;       // 50000
    int E = in_sizes[1] / 2;          // 800000
    int nblk = (n + SCAN_B - 1) / SCAN_B;

    static int s_inited = 0;
    static cudaStream_t s_side;
    static cudaEvent_t  s_fork, s_join;
    if (!s_inited) {
        cudaStreamCreateWithFlags(&s_side, cudaStreamNonBlocking);
        cudaEventCreateWithFlags(&s_fork, cudaEventDisableTiming);
        cudaEventCreateWithFlags(&s_join, cudaEventDisableTiming);
        s_inited = 1;
    }

    // Fork: gemm (x,W -> g_h/g_hh) is independent of the CSR build chain.
    cudaEventRecord(s_fork, 0);
    cudaStreamWaitEvent(s_side, s_fork, 0);
    k_gemm<<<(n + 63) / 64, 256, 0, s_side>>>(x, W, n);
    cudaEventRecord(s_join, s_side);

    // Main stream: CSR build.
    k_init <<<(n + 255) / 256, 256>>>((const unsigned int*)ei, n);
    k_deg  <<<(E + 255) / 256, 256>>>(ei, E);
    k_scanA<<<nblk, SCAN_B>>>(n);
    k_scanB<<<nblk, SCAN_B>>>(n, E);
    k_fill <<<(E + 255) / 256, 256>>>(ei, E);

    // Join, then aggregate + finalize.
    cudaStreamWaitEvent(0, s_join, 0);
    k_agg  <<<(n + 7) / 8, 256>>>(n);
    k_final<<<(n + 7) / 8, 256>>>(gamma, beta, out, n);
}